// round 5
// baseline (speedup 1.0000x reference)
#include <cuda_runtime.h>
#include <mma.h>
#include <stdint.h>

using namespace nvcuda;

// Problem constants (fixed by the reference)
#define MAXN 100000
#define MAXE 600000
#define F 128
#define BN_EPS 1e-5f

#define SCAN_BLK 4096            // elements per scan block (1024 thr x 4)
#define NBMAX 32                 // max scan blocks (ceil(100000/4096)=25)

// ---------------- device scratch (no allocations allowed) ----------------
__device__ __align__(16) float g_h[(size_t)MAXN * F];     // h = x @ W
__device__ __align__(16) float g_agg[(size_t)MAXN * F];   // relu(agg)
__device__ int   g_deg[MAXN + 4];
__device__ int   g_off[MAXN + 4];
__device__ int   g_cur[MAXN];
__device__ int   g_src[MAXE];
__device__ float g_dinv[MAXN];
__device__ int   g_bsum[NBMAX];
__device__ float g_sum[F];
__device__ float g_sumsq[F];
__device__ float g_scale[F];
__device__ float g_shift[F];
__device__ int   g_is64;

// ---------------- detect edge_index dtype (int64 vs silently-int32) -------
__global__ void detect_kernel(const void* ei, int n) {
    if (threadIdx.x == 0 && blockIdx.x == 0) {
        const long long* p = (const long long*)ei;
        int ok = 1;
#pragma unroll
        for (int i = 0; i < 16; i++) {
            long long v = p[i];
            if (v < 0 || v >= n) { ok = 0; break; }
        }
        g_is64 = ok;
    }
}

// ---------------- init ----------------
__global__ void init_kernel(int n) {
    int i = blockIdx.x * blockDim.x + threadIdx.x;
    if (i < n) g_deg[i] = 0;
    if (i < F) { g_sum[i] = 0.f; g_sumsq[i] = 0.f; }
}

// ---------------- degree histogram over destination (col) ----------------
__global__ void deg_kernel(const void* __restrict__ ei, int E) {
    int e = blockIdx.x * blockDim.x + threadIdx.x;
    if (e < E) {
        int c;
        if (g_is64) c = (int)((const long long*)ei)[E + e];
        else        c = ((const int*)ei)[E + e];
        atomicAdd(&g_deg[c], 1);
    }
}

// ---------------- 3-phase scan ----------------
// phase 1: block-local exclusive scan of deg (4096 elems/block) + dinv
__global__ void scan1_kernel(int n) {
    __shared__ int wsum[32];
    const int t = threadIdx.x;
    const int lane = t & 31;
    const int w = t >> 5;
    const int idx = blockIdx.x * SCAN_BLK + t * 4;

    int d0 = 0, d1 = 0, d2 = 0, d3 = 0;
    if (idx + 3 < n) {
        int4 dd = *(const int4*)&g_deg[idx];
        d0 = dd.x; d1 = dd.y; d2 = dd.z; d3 = dd.w;
    } else {
        if (idx + 0 < n) d0 = g_deg[idx + 0];
        if (idx + 1 < n) d1 = g_deg[idx + 1];
        if (idx + 2 < n) d2 = g_deg[idx + 2];
        if (idx + 3 < n) d3 = g_deg[idx + 3];
    }
    int s = d0 + d1 + d2 + d3;
    int v = s;
#pragma unroll
    for (int o = 1; o < 32; o <<= 1) {
        int a = __shfl_up_sync(0xffffffffu, v, o);
        if (lane >= o) v += a;
    }
    if (lane == 31) wsum[w] = v;
    __syncthreads();
    if (w == 0) {
        int sv = wsum[lane];
#pragma unroll
        for (int o = 1; o < 32; o <<= 1) {
            int a = __shfl_up_sync(0xffffffffu, sv, o);
            if (lane >= o) sv += a;
        }
        wsum[lane] = sv;
    }
    __syncthreads();
    int excl = (w ? wsum[w - 1] : 0) + v - s;

    if (idx + 3 < n) {
        int4 oo = make_int4(excl, excl + d0, excl + d0 + d1, excl + d0 + d1 + d2);
        *(int4*)&g_off[idx] = oo;
        g_dinv[idx + 0] = rsqrtf((float)(d0 + 1));
        g_dinv[idx + 1] = rsqrtf((float)(d1 + 1));
        g_dinv[idx + 2] = rsqrtf((float)(d2 + 1));
        g_dinv[idx + 3] = rsqrtf((float)(d3 + 1));
    } else {
        int e = excl;
        if (idx + 0 < n) { g_off[idx + 0] = e; g_dinv[idx + 0] = rsqrtf((float)(d0 + 1)); e += d0; }
        if (idx + 1 < n) { g_off[idx + 1] = e; g_dinv[idx + 1] = rsqrtf((float)(d1 + 1)); e += d1; }
        if (idx + 2 < n) { g_off[idx + 2] = e; g_dinv[idx + 2] = rsqrtf((float)(d2 + 1)); e += d2; }
        if (idx + 3 < n) { g_off[idx + 3] = e; g_dinv[idx + 3] = rsqrtf((float)(d3 + 1)); }
    }
    if (t == 0) g_bsum[blockIdx.x] = 0;   // will be overwritten below for all blocks
    __syncthreads();
    if (t == 0) g_bsum[blockIdx.x] = wsum[31];
}

// phase 2: exclusive scan of block sums (single warp)
__global__ void scan2_kernel(int nb) {
    int lane = threadIdx.x;
    int v = (lane < nb) ? g_bsum[lane] : 0;
    int orig = v;
#pragma unroll
    for (int o = 1; o < 32; o <<= 1) {
        int a = __shfl_up_sync(0xffffffffu, v, o);
        if (lane >= o) v += a;
    }
    if (lane < nb) g_bsum[lane] = v - orig;
}

// phase 3: add block base, init cursor
__global__ void scan3_kernel(int n) {
    int i = blockIdx.x * blockDim.x + threadIdx.x;
    if (i < n) {
        int o = g_off[i] + g_bsum[i >> 12];
        g_off[i] = o;
        g_cur[i] = o;
    }
}

// ---------------- CSR fill ----------------
__global__ void fill_kernel(const void* __restrict__ ei, int E) {
    int e = blockIdx.x * blockDim.x + threadIdx.x;
    if (e < E) {
        int r, c;
        if (g_is64) {
            r = (int)((const long long*)ei)[e];
            c = (int)((const long long*)ei)[E + e];
        } else {
            r = ((const int*)ei)[e];
            c = ((const int*)ei)[E + e];
        }
        int p = atomicAdd(&g_cur[c], 1);
        g_src[p] = r;
    }
}

// ---------------- tensor-core GEMM (tf32x2): Y[n,128] = X[n,128] @ W ------
// block = 256 threads (8 warps), block tile 64 rows x 128 cols.
// warp grid 2x4: warp tile 32 rows x 32 cols = 2x2 wmma 16x16x8 fragments.
// K chunked by 16. hi/lo tf32 decomposition: ah*bh + ah*bl + al*bh.
#define TCM 64
#define KC 16
#define LDA 24     // 16 + 8 pad (mult of 8, conflict-shifting)
#define LDB 136    // 128 + 8 pad
#define LDC 24
// smem floats: xs_hi 64*24=1536 | xs_lo 1536 | ws_hi 16*136=2176 | ws_lo 2176
#define SM_XS_LO 1536
#define SM_WS_HI 3072
#define SM_WS_LO 5248
#define SM_TOTAL 7424   // 29.7 KB

template <bool TO_GH>
__global__ void gemm_tc_kernel(const float* __restrict__ X,
                               const float* __restrict__ Wm,
                               float* __restrict__ Yext, int n) {
    __shared__ __align__(32) float smem[SM_TOTAL];
    float* xs_hi = smem;
    float* xs_lo = smem + SM_XS_LO;
    float* ws_hi = smem + SM_WS_HI;
    float* ws_lo = smem + SM_WS_LO;

    const int t = threadIdx.x;
    const int w = t >> 5;
    const int lane = t & 31;
    const int wr = w >> 2;     // 0..1
    const int wc = w & 3;      // 0..3
    const int block_row = blockIdx.x * TCM;

    wmma::fragment<wmma::accumulator, 16, 16, 8, float> acc[2][2];
#pragma unroll
    for (int r = 0; r < 2; r++)
#pragma unroll
        for (int c = 0; c < 2; c++) wmma::fill_fragment(acc[r][c], 0.f);

    for (int kc = 0; kc < F; kc += KC) {
        __syncthreads();
        // X chunk: 64 rows x 16 cols; one float4 per thread
        {
            int r = t >> 2;
            int c4 = t & 3;
            int gr = block_row + r;
            float4 v = make_float4(0.f, 0.f, 0.f, 0.f);
            if (gr < n) v = *(const float4*)&X[(size_t)gr * F + kc + c4 * 4];
            float hx = wmma::__float_to_tf32(v.x);
            float hy = wmma::__float_to_tf32(v.y);
            float hz = wmma::__float_to_tf32(v.z);
            float hw = wmma::__float_to_tf32(v.w);
            *(float4*)&xs_hi[r * LDA + c4 * 4] = make_float4(hx, hy, hz, hw);
            *(float4*)&xs_lo[r * LDA + c4 * 4] = make_float4(
                wmma::__float_to_tf32(v.x - hx), wmma::__float_to_tf32(v.y - hy),
                wmma::__float_to_tf32(v.z - hz), wmma::__float_to_tf32(v.w - hw));
        }
        // W chunk: 16 rows x 128 cols; two float4 per thread
#pragma unroll
        for (int j = 0; j < 2; j++) {
            int idx = j * 256 + t;
            int r = idx >> 5;
            int c4 = idx & 31;
            float4 v = *(const float4*)&Wm[(size_t)(kc + r) * F + c4 * 4];
            float hx = wmma::__float_to_tf32(v.x);
            float hy = wmma::__float_to_tf32(v.y);
            float hz = wmma::__float_to_tf32(v.z);
            float hw = wmma::__float_to_tf32(v.w);
            *(float4*)&ws_hi[r * LDB + c4 * 4] = make_float4(hx, hy, hz, hw);
            *(float4*)&ws_lo[r * LDB + c4 * 4] = make_float4(
                wmma::__float_to_tf32(v.x - hx), wmma::__float_to_tf32(v.y - hy),
                wmma::__float_to_tf32(v.z - hz), wmma::__float_to_tf32(v.w - hw));
        }
        __syncthreads();

#pragma unroll
        for (int kk = 0; kk < KC; kk += 8) {
            wmma::fragment<wmma::matrix_a, 16, 16, 8, wmma::precision::tf32, wmma::row_major> ah[2], al[2];
            wmma::fragment<wmma::matrix_b, 16, 16, 8, wmma::precision::tf32, wmma::row_major> bh[2], bl[2];
#pragma unroll
            for (int r = 0; r < 2; r++) {
                const float* pa = xs_hi + (wr * 32 + r * 16) * LDA + kk;
                wmma::load_matrix_sync(ah[r], pa, LDA);
                wmma::load_matrix_sync(al[r], pa + SM_XS_LO, LDA);
            }
#pragma unroll
            for (int c = 0; c < 2; c++) {
                const float* pb = ws_hi + kk * LDB + wc * 32 + c * 16;
                wmma::load_matrix_sync(bh[c], pb, LDB);
                wmma::load_matrix_sync(bl[c], pb + (SM_WS_LO - SM_WS_HI), LDB);
            }
#pragma unroll
            for (int r = 0; r < 2; r++)
#pragma unroll
                for (int c = 0; c < 2; c++) {
                    wmma::mma_sync(acc[r][c], ah[r], bh[c], acc[r][c]);
                    wmma::mma_sync(acc[r][c], ah[r], bl[c], acc[r][c]);
                    wmma::mma_sync(acc[r][c], al[r], bh[c], acc[r][c]);
                }
        }
    }

    // epilogue: stage each fragment in smem, guarded vectorized copy-out
    __syncthreads();
    float* buf = smem + w * 16 * LDC;
    float* Y = TO_GH ? g_h : Yext;
#pragma unroll
    for (int r = 0; r < 2; r++)
#pragma unroll
        for (int c = 0; c < 2; c++) {
            wmma::store_matrix_sync(buf, acc[r][c], LDC, wmma::mem_row_major);
            __syncwarp();
            int row0 = block_row + wr * 32 + r * 16;
            int col0 = wc * 32 + c * 16;
#pragma unroll
            for (int it = 0; it < 2; it++) {
                int e = it * 32 + lane;       // 0..63
                int rr = e >> 2, cc = e & 3;
                int gr = row0 + rr;
                if (gr < n)
                    *(float4*)&Y[(size_t)gr * F + col0 + cc * 4] =
                        *(const float4*)&buf[rr * LDC + cc * 4];
            }
            __syncwarp();
        }
}

// ---------------- aggregate (gather) + self-loop + bias + ReLU + BN stats --
__global__ void aggregate_kernel(const float* __restrict__ b, int n) {
    __shared__ float bsum[F];
    __shared__ float bsq[F];
    const int t = threadIdx.x;
    if (t < F) { bsum[t] = 0.f; bsq[t] = 0.f; }
    __syncthreads();

    const int node = (blockIdx.x * blockDim.x + t) >> 5;
    const int lane = t & 31;

    if (node < n) {
        const float4* h4 = (const float4*)g_h;
        float dc = g_dinv[node];
        float dc2 = dc * dc;
        int j = g_off[node];
        int end = j + g_deg[node];

        float4 acc = h4[(size_t)node * 32 + lane];
        float4 bv = ((const float4*)b)[lane];
        acc.x = fmaf(acc.x, dc2, bv.x);
        acc.y = fmaf(acc.y, dc2, bv.y);
        acc.z = fmaf(acc.z, dc2, bv.z);
        acc.w = fmaf(acc.w, dc2, bv.w);

        for (; j < end; j++) {
            int r = g_src[j];
            float nrm = dc * g_dinv[r];
            float4 v = h4[(size_t)r * 32 + lane];
            acc.x = fmaf(v.x, nrm, acc.x);
            acc.y = fmaf(v.y, nrm, acc.y);
            acc.z = fmaf(v.z, nrm, acc.z);
            acc.w = fmaf(v.w, nrm, acc.w);
        }
        acc.x = fmaxf(acc.x, 0.f);
        acc.y = fmaxf(acc.y, 0.f);
        acc.z = fmaxf(acc.z, 0.f);
        acc.w = fmaxf(acc.w, 0.f);
        ((float4*)g_agg)[(size_t)node * 32 + lane] = acc;

        int f0 = lane * 4;
        atomicAdd(&bsum[f0 + 0], acc.x);
        atomicAdd(&bsum[f0 + 1], acc.y);
        atomicAdd(&bsum[f0 + 2], acc.z);
        atomicAdd(&bsum[f0 + 3], acc.w);
        atomicAdd(&bsq[f0 + 0], acc.x * acc.x);
        atomicAdd(&bsq[f0 + 1], acc.y * acc.y);
        atomicAdd(&bsq[f0 + 2], acc.z * acc.z);
        atomicAdd(&bsq[f0 + 3], acc.w * acc.w);
    }
    __syncthreads();
    if (t < F) {
        atomicAdd(&g_sum[t], bsum[t]);
        atomicAdd(&g_sumsq[t], bsq[t]);
    }
}

// ---------------- fold mean/var/gamma/beta into scale/shift ----------------
__global__ void finalize_stats_kernel(const float* __restrict__ gamma,
                                      const float* __restrict__ beta, int n) {
    int f = threadIdx.x;
    if (f < F) {
        float inv_n = 1.f / (float)n;
        float mean = g_sum[f] * inv_n;
        float var = g_sumsq[f] * inv_n - mean * mean;
        float istd = rsqrtf(var + BN_EPS);
        float sc = gamma[f] * istd;
        g_scale[f] = sc;
        g_shift[f] = beta[f] - mean * sc;
    }
}

// ---------------- final: out += r*scale + shift + b_res --------------------
__global__ void final_kernel(float* __restrict__ out,
                             const float* __restrict__ b_res, int n) {
    int tid = blockIdx.x * blockDim.x + threadIdx.x;
    if (tid >= n * (F / 4)) return;
    int s = tid & 31;
    float4 a = ((const float4*)g_agg)[tid];        // already ReLU'd
    float4 sc = ((const float4*)g_scale)[s];
    float4 sh = ((const float4*)g_shift)[s];
    float4 br = ((const float4*)b_res)[s];
    float4 o = ((float4*)out)[tid];
    o.x += a.x * sc.x + sh.x + br.x;
    o.y += a.y * sc.y + sh.y + br.y;
    o.z += a.z * sc.z + sh.z + br.z;
    o.w += a.w * sc.w + sh.w + br.w;
    ((float4*)out)[tid] = o;
}

// ---------------- launch (kernel launches ONLY) ----------------------------
extern "C" void kernel_launch(void* const* d_in, const int* in_sizes, int n_in,
                              void* d_out, int out_size) {
    const float* x        = (const float*)d_in[0];
    const void*  ei       = d_in[1];
    const float* W        = (const float*)d_in[2];
    const float* b        = (const float*)d_in[3];
    const float* gamma    = (const float*)d_in[4];
    const float* beta     = (const float*)d_in[5];
    const float* W_res    = (const float*)d_in[6];
    const float* b_res    = (const float*)d_in[7];
    float* out            = (float*)d_out;

    const int n = in_sizes[0] / F;
    const int E = in_sizes[1] / 2;
    const int nb = (n + SCAN_BLK - 1) / SCAN_BLK;

    const int T = 256;
    detect_kernel<<<1, 32>>>(ei, n);
    init_kernel<<<(n + T - 1) / T, T>>>(n);
    deg_kernel<<<(E + T - 1) / T, T>>>(ei, E);
    scan1_kernel<<<nb, 1024>>>(n);
    scan2_kernel<<<1, 32>>>(nb);
    scan3_kernel<<<(n + T - 1) / T, T>>>(n);
    fill_kernel<<<(E + T - 1) / T, T>>>(ei, E);
    // h = x @ W (to g_h symbol), res = x @ W_res (to d_out)
    gemm_tc_kernel<true><<<(n + TCM - 1) / TCM, T>>>(x, W, nullptr, n);
    gemm_tc_kernel<false><<<(n + TCM - 1) / TCM, T>>>(x, W_res, out, n);
    // gather-aggregate + ReLU + stats
    {
        long long work = (long long)n * 32;
        aggregate_kernel<<<(int)((work + T - 1) / T), T>>>(b, n);
    }
    finalize_stats_kernel<<<1, F>>>(gamma, beta, n);
    {
        int work = n * (F / 4);
        final_kernel<<<(work + T - 1) / T, T>>>(out, b_res, n);
    }
}

// round 6
// speedup vs baseline: 1.2239x; 1.2239x over previous
#include <cuda_runtime.h>
#include <stdint.h>

// Problem constants (fixed by the reference)
#define MAXN 100000
#define MAXE 600000
#define F 128
#define BN_EPS 1e-5f

#define SCAN_BLK 4096
#define NBMAX 32

// ---------------- device scratch (no allocations allowed) ----------------
__device__ __align__(16) float g_h[(size_t)MAXN * F];     // h = x @ W
__device__ __align__(16) float g_agg[(size_t)MAXN * F];   // relu(agg)
__device__ int   g_deg[MAXN + 4];
__device__ int   g_off[MAXN + 4];
__device__ int   g_cur[MAXN];
__device__ int   g_src[MAXE];
__device__ float g_dinv[MAXN];
__device__ int   g_bsum[NBMAX];
__device__ float g_sum[F];
__device__ float g_sumsq[F];
__device__ float g_scale[F];
__device__ float g_shift[F];
__device__ int   g_is64;

// ---------------- packed f32x2 helpers ----------------
#define PACK_DUP(dst, f) \
    asm("mov.b64 %0, {%1, %1};" : "=l"(dst) : "r"(__float_as_uint(f)))
#define FMA2(acc, a, b) \
    asm("fma.rn.f32x2 %0, %1, %2, %0;" : "+l"(acc) : "l"(a), "l"(b))
#define UNPACK2(lo, hi, src) \
    asm("mov.b64 {%0, %1}, %2;" : "=r"(lo), "=r"(hi) : "l"(src))

// ---------------- detect edge_index dtype (int64 vs silently-int32) -------
__global__ void detect_kernel(const void* ei, int n) {
    if (threadIdx.x == 0 && blockIdx.x == 0) {
        const long long* p = (const long long*)ei;
        int ok = 1;
#pragma unroll
        for (int i = 0; i < 16; i++) {
            long long v = p[i];
            if (v < 0 || v >= n) { ok = 0; break; }
        }
        g_is64 = ok;
    }
}

// ---------------- init ----------------
__global__ void init_kernel(int n) {
    int i = blockIdx.x * blockDim.x + threadIdx.x;
    if (i < n) g_deg[i] = 0;
    if (i < F) { g_sum[i] = 0.f; g_sumsq[i] = 0.f; }
}

// ---------------- degree histogram over destination (col) ----------------
__global__ void deg_kernel(const void* __restrict__ ei, int E) {
    int e = blockIdx.x * blockDim.x + threadIdx.x;
    if (e < E) {
        int c;
        if (g_is64) c = (int)((const long long*)ei)[E + e];
        else        c = ((const int*)ei)[E + e];
        atomicAdd(&g_deg[c], 1);
    }
}

// ---------------- 3-phase scan ----------------
__global__ void scan1_kernel(int n) {
    __shared__ int wsum[32];
    const int t = threadIdx.x;
    const int lane = t & 31;
    const int w = t >> 5;
    const int idx = blockIdx.x * SCAN_BLK + t * 4;

    int d0 = 0, d1 = 0, d2 = 0, d3 = 0;
    if (idx + 3 < n) {
        int4 dd = *(const int4*)&g_deg[idx];
        d0 = dd.x; d1 = dd.y; d2 = dd.z; d3 = dd.w;
    } else {
        if (idx + 0 < n) d0 = g_deg[idx + 0];
        if (idx + 1 < n) d1 = g_deg[idx + 1];
        if (idx + 2 < n) d2 = g_deg[idx + 2];
        if (idx + 3 < n) d3 = g_deg[idx + 3];
    }
    int s = d0 + d1 + d2 + d3;
    int v = s;
#pragma unroll
    for (int o = 1; o < 32; o <<= 1) {
        int a = __shfl_up_sync(0xffffffffu, v, o);
        if (lane >= o) v += a;
    }
    if (lane == 31) wsum[w] = v;
    __syncthreads();
    if (w == 0) {
        int sv = wsum[lane];
#pragma unroll
        for (int o = 1; o < 32; o <<= 1) {
            int a = __shfl_up_sync(0xffffffffu, sv, o);
            if (lane >= o) sv += a;
        }
        wsum[lane] = sv;
    }
    __syncthreads();
    int excl = (w ? wsum[w - 1] : 0) + v - s;

    if (idx + 3 < n) {
        int4 oo = make_int4(excl, excl + d0, excl + d0 + d1, excl + d0 + d1 + d2);
        *(int4*)&g_off[idx] = oo;
        g_dinv[idx + 0] = rsqrtf((float)(d0 + 1));
        g_dinv[idx + 1] = rsqrtf((float)(d1 + 1));
        g_dinv[idx + 2] = rsqrtf((float)(d2 + 1));
        g_dinv[idx + 3] = rsqrtf((float)(d3 + 1));
    } else {
        int e = excl;
        if (idx + 0 < n) { g_off[idx + 0] = e; g_dinv[idx + 0] = rsqrtf((float)(d0 + 1)); e += d0; }
        if (idx + 1 < n) { g_off[idx + 1] = e; g_dinv[idx + 1] = rsqrtf((float)(d1 + 1)); e += d1; }
        if (idx + 2 < n) { g_off[idx + 2] = e; g_dinv[idx + 2] = rsqrtf((float)(d2 + 1)); e += d2; }
        if (idx + 3 < n) { g_off[idx + 3] = e; g_dinv[idx + 3] = rsqrtf((float)(d3 + 1)); }
    }
    if (t == 0) g_bsum[blockIdx.x] = wsum[31];
}

__global__ void scan2_kernel(int nb) {
    int lane = threadIdx.x;
    int v = (lane < nb) ? g_bsum[lane] : 0;
    int orig = v;
#pragma unroll
    for (int o = 1; o < 32; o <<= 1) {
        int a = __shfl_up_sync(0xffffffffu, v, o);
        if (lane >= o) v += a;
    }
    if (lane < nb) g_bsum[lane] = v - orig;
}

__global__ void scan3_kernel(int n) {
    int i = blockIdx.x * blockDim.x + threadIdx.x;
    if (i < n) {
        int o = g_off[i] + g_bsum[i >> 12];
        g_off[i] = o;
        g_cur[i] = o;
    }
}

// ---------------- CSR fill ----------------
__global__ void fill_kernel(const void* __restrict__ ei, int E) {
    int e = blockIdx.x * blockDim.x + threadIdx.x;
    if (e < E) {
        int r, c;
        if (g_is64) {
            r = (int)((const long long*)ei)[e];
            c = (int)((const long long*)ei)[E + e];
        } else {
            r = ((const int*)ei)[e];
            c = ((const int*)ei)[E + e];
        }
        int p = atomicAdd(&g_cur[c], 1);
        g_src[p] = r;
    }
}

// ---------------- fused dual GEMM via packed fp32 FFMA2 -------------------
// Computes h = x@W (-> g_h) and res = x@W_res + b_res (-> d_out) in one pass.
// Block: 256 threads, tile 64 rows x 256 cols (128 for each weight matrix).
// K chunked by 32. x stored transposed in smem so consecutive row pairs load
// as packed u64; accumulation via fma.rn.f32x2 (2 MACs per issue, full fp32).
#define TCM 64
#define KC 32
#define LDR 64     // xs_t row stride (floats)

__global__ void gemm_dual_kernel(const float* __restrict__ X,
                                 const float* __restrict__ Wm,
                                 const float* __restrict__ Wres,
                                 const float* __restrict__ b_res,
                                 float* __restrict__ out, int n) {
    __shared__ float xs_t[KC * LDR];     // 8 KB  (k-major: xs_t[k][row])
    __shared__ float ws[KC * 256];       // 32 KB (ws[k][c]; c<128 W, c>=128 W_res)

    const int t = threadIdx.x;
    const int tx = t & 31;
    const int ty = t >> 5;
    const int c0 = tx * 8;               // 8 output cols
    const int r0 = ty * 8;               // 8 rows (4 packed pairs)
    const int block_row = blockIdx.x * TCM;

    unsigned long long acc[4][8];
#pragma unroll
    for (int i = 0; i < 4; i++)
#pragma unroll
        for (int j = 0; j < 8; j++) acc[i][j] = 0ULL;

    for (int kc = 0; kc < F; kc += KC) {
        __syncthreads();
        // x chunk: 64 rows x 32 k, transposed store
#pragma unroll
        for (int jj = 0; jj < 2; jj++) {
            int idx = jj * 256 + t;          // 0..511
            int row = idx >> 3;
            int c4 = idx & 7;
            int gr = block_row + row;
            float4 v = make_float4(0.f, 0.f, 0.f, 0.f);
            if (gr < n) v = *(const float4*)&X[(size_t)gr * F + kc + c4 * 4];
            xs_t[(c4 * 4 + 0) * LDR + row] = v.x;
            xs_t[(c4 * 4 + 1) * LDR + row] = v.y;
            xs_t[(c4 * 4 + 2) * LDR + row] = v.z;
            xs_t[(c4 * 4 + 3) * LDR + row] = v.w;
        }
        // weight chunk: 32 k x 128 cols from each matrix
#pragma unroll
        for (int jj = 0; jj < 4; jj++) {
            int idx = jj * 256 + t;          // 0..1023
            int k = idx >> 5;
            int c4 = idx & 31;
            *(float4*)&ws[k * 256 + c4 * 4] =
                *(const float4*)&Wm[(size_t)(kc + k) * F + c4 * 4];
            *(float4*)&ws[k * 256 + 128 + c4 * 4] =
                *(const float4*)&Wres[(size_t)(kc + k) * F + c4 * 4];
        }
        __syncthreads();

#pragma unroll 8
        for (int k = 0; k < KC; k++) {
            // 4 packed row-pairs of x (broadcast across lanes of the warp)
            ulonglong2 xpa = *(const ulonglong2*)&xs_t[k * LDR + r0];
            ulonglong2 xpb = *(const ulonglong2*)&xs_t[k * LDR + r0 + 4];
            unsigned long long xp0 = xpa.x, xp1 = xpa.y, xp2 = xpb.x, xp3 = xpb.y;
            // 8 weights, duplicated into packed pairs
            float4 wa = *(const float4*)&ws[k * 256 + c0];
            float4 wb = *(const float4*)&ws[k * 256 + c0 + 4];
            unsigned long long wp[8];
            PACK_DUP(wp[0], wa.x); PACK_DUP(wp[1], wa.y);
            PACK_DUP(wp[2], wa.z); PACK_DUP(wp[3], wa.w);
            PACK_DUP(wp[4], wb.x); PACK_DUP(wp[5], wb.y);
            PACK_DUP(wp[6], wb.z); PACK_DUP(wp[7], wb.w);
#pragma unroll
            for (int j = 0; j < 8; j++) {
                FMA2(acc[0][j], xp0, wp[j]);
                FMA2(acc[1][j], xp1, wp[j]);
                FMA2(acc[2][j], xp2, wp[j]);
                FMA2(acc[3][j], xp3, wp[j]);
            }
        }
    }

    // epilogue
    const bool second = (tx >= 16);
    float br[8] = {0, 0, 0, 0, 0, 0, 0, 0};
    if (second) {
        float4 ba = *(const float4*)&b_res[c0 - 128];
        float4 bb = *(const float4*)&b_res[c0 - 124];
        br[0] = ba.x; br[1] = ba.y; br[2] = ba.z; br[3] = ba.w;
        br[4] = bb.x; br[5] = bb.y; br[6] = bb.z; br[7] = bb.w;
    }
    float* Y = second ? out : g_h;
    const int ycol = second ? (c0 - 128) : c0;

#pragma unroll
    for (int i = 0; i < 4; i++) {
        unsigned int lo[8], hi[8];
#pragma unroll
        for (int j = 0; j < 8; j++) UNPACK2(lo[j], hi[j], acc[i][j]);
        int ra = block_row + r0 + 2 * i;
        int rb = ra + 1;
        if (ra < n) {
            float4 o0 = make_float4(__uint_as_float(lo[0]) + br[0],
                                    __uint_as_float(lo[1]) + br[1],
                                    __uint_as_float(lo[2]) + br[2],
                                    __uint_as_float(lo[3]) + br[3]);
            float4 o1 = make_float4(__uint_as_float(lo[4]) + br[4],
                                    __uint_as_float(lo[5]) + br[5],
                                    __uint_as_float(lo[6]) + br[6],
                                    __uint_as_float(lo[7]) + br[7]);
            *(float4*)&Y[(size_t)ra * F + ycol] = o0;
            *(float4*)&Y[(size_t)ra * F + ycol + 4] = o1;
        }
        if (rb < n) {
            float4 o0 = make_float4(__uint_as_float(hi[0]) + br[0],
                                    __uint_as_float(hi[1]) + br[1],
                                    __uint_as_float(hi[2]) + br[2],
                                    __uint_as_float(hi[3]) + br[3]);
            float4 o1 = make_float4(__uint_as_float(hi[4]) + br[4],
                                    __uint_as_float(hi[5]) + br[5],
                                    __uint_as_float(hi[6]) + br[6],
                                    __uint_as_float(hi[7]) + br[7]);
            *(float4*)&Y[(size_t)rb * F + ycol] = o0;
            *(float4*)&Y[(size_t)rb * F + ycol + 4] = o1;
        }
    }
}

// ---------------- aggregate (gather) + self-loop + bias + ReLU + BN stats --
__global__ void aggregate_kernel(const float* __restrict__ b, int n) {
    __shared__ float bsum[F];
    __shared__ float bsq[F];
    const int t = threadIdx.x;
    if (t < F) { bsum[t] = 0.f; bsq[t] = 0.f; }
    __syncthreads();

    const int node = (blockIdx.x * blockDim.x + t) >> 5;
    const int lane = t & 31;

    if (node < n) {
        const float4* h4 = (const float4*)g_h;
        float dc = g_dinv[node];
        float dc2 = dc * dc;
        int j = g_off[node];
        int end = j + g_deg[node];

        float4 acc = h4[(size_t)node * 32 + lane];
        float4 bv = ((const float4*)b)[lane];
        acc.x = fmaf(acc.x, dc2, bv.x);
        acc.y = fmaf(acc.y, dc2, bv.y);
        acc.z = fmaf(acc.z, dc2, bv.z);
        acc.w = fmaf(acc.w, dc2, bv.w);

        for (; j < end; j++) {
            int r = g_src[j];
            float nrm = dc * g_dinv[r];
            float4 v = h4[(size_t)r * 32 + lane];
            acc.x = fmaf(v.x, nrm, acc.x);
            acc.y = fmaf(v.y, nrm, acc.y);
            acc.z = fmaf(v.z, nrm, acc.z);
            acc.w = fmaf(v.w, nrm, acc.w);
        }
        acc.x = fmaxf(acc.x, 0.f);
        acc.y = fmaxf(acc.y, 0.f);
        acc.z = fmaxf(acc.z, 0.f);
        acc.w = fmaxf(acc.w, 0.f);
        ((float4*)g_agg)[(size_t)node * 32 + lane] = acc;

        int f0 = lane * 4;
        atomicAdd(&bsum[f0 + 0], acc.x);
        atomicAdd(&bsum[f0 + 1], acc.y);
        atomicAdd(&bsum[f0 + 2], acc.z);
        atomicAdd(&bsum[f0 + 3], acc.w);
        atomicAdd(&bsq[f0 + 0], acc.x * acc.x);
        atomicAdd(&bsq[f0 + 1], acc.y * acc.y);
        atomicAdd(&bsq[f0 + 2], acc.z * acc.z);
        atomicAdd(&bsq[f0 + 3], acc.w * acc.w);
    }
    __syncthreads();
    if (t < F) {
        atomicAdd(&g_sum[t], bsum[t]);
        atomicAdd(&g_sumsq[t], bsq[t]);
    }
}

// ---------------- fold mean/var/gamma/beta into scale/shift ----------------
__global__ void finalize_stats_kernel(const float* __restrict__ gamma,
                                      const float* __restrict__ beta, int n) {
    int f = threadIdx.x;
    if (f < F) {
        float inv_n = 1.f / (float)n;
        float mean = g_sum[f] * inv_n;
        float var = g_sumsq[f] * inv_n - mean * mean;
        float istd = rsqrtf(var + BN_EPS);
        float sc = gamma[f] * istd;
        g_scale[f] = sc;
        g_shift[f] = beta[f] - mean * sc;
    }
}

// ---------------- final: out += r*scale + shift (out holds res+b_res) -----
__global__ void final_kernel(float* __restrict__ out, int n) {
    int tid = blockIdx.x * blockDim.x + threadIdx.x;
    if (tid >= n * (F / 4)) return;
    int s = tid & 31;
    float4 a = ((const float4*)g_agg)[tid];        // already ReLU'd
    float4 sc = ((const float4*)g_scale)[s];
    float4 sh = ((const float4*)g_shift)[s];
    float4 o = ((float4*)out)[tid];
    o.x += a.x * sc.x + sh.x;
    o.y += a.y * sc.y + sh.y;
    o.z += a.z * sc.z + sh.z;
    o.w += a.w * sc.w + sh.w;
    ((float4*)out)[tid] = o;
}

// ---------------- launch (kernel launches ONLY) ----------------------------
extern "C" void kernel_launch(void* const* d_in, const int* in_sizes, int n_in,
                              void* d_out, int out_size) {
    const float* x        = (const float*)d_in[0];
    const void*  ei       = d_in[1];
    const float* W        = (const float*)d_in[2];
    const float* b        = (const float*)d_in[3];
    const float* gamma    = (const float*)d_in[4];
    const float* beta     = (const float*)d_in[5];
    const float* W_res    = (const float*)d_in[6];
    const float* b_res    = (const float*)d_in[7];
    float* out            = (float*)d_out;

    const int n = in_sizes[0] / F;
    const int E = in_sizes[1] / 2;
    const int nb = (n + SCAN_BLK - 1) / SCAN_BLK;

    const int T = 256;
    detect_kernel<<<1, 32>>>(ei, n);
    init_kernel<<<(n + T - 1) / T, T>>>(n);
    deg_kernel<<<(E + T - 1) / T, T>>>(ei, E);
    scan1_kernel<<<nb, 1024>>>(n);
    scan2_kernel<<<1, 32>>>(nb);
    scan3_kernel<<<(n + T - 1) / T, T>>>(n);
    fill_kernel<<<(E + T - 1) / T, T>>>(ei, E);
    // fused: h = x@W -> g_h ; out = x@W_res + b_res
    gemm_dual_kernel<<<(n + TCM - 1) / TCM, T>>>(x, W, W_res, b_res, out, n);
    // gather-aggregate + ReLU + stats
    {
        long long work = (long long)n * 32;
        aggregate_kernel<<<(int)((work + T - 1) / T), T>>>(b, n);
    }
    finalize_stats_kernel<<<1, F>>>(gamma, beta, n);
    {
        int work = n * (F / 4);
        final_kernel<<<(work + T - 1) / T, T>>>(out, n);
    }
}

// round 8
// speedup vs baseline: 1.6684x; 1.3632x over previous
#include <cuda_runtime.h>
#include <cuda_bf16.h>
#include <stdint.h>

// Problem constants (fixed by the reference)
#define MAXN 100000
#define MAXE 600000
#define F 128
#define BN_EPS 1e-5f

#define SCAN_BLK 4096
#define NBMAX 32

// ---------------- device scratch (no allocations allowed) ----------------
__device__ __align__(16) float g_h[(size_t)MAXN * F];     // h = x @ W
__device__ __align__(16) float g_agg[(size_t)MAXN * F];   // relu(agg)
__device__ int   g_deg[MAXN + 4];
__device__ int   g_off[MAXN + 4];
__device__ int   g_cur[MAXN];
__device__ int   g_src[MAXE];
__device__ float g_dinv[MAXN];
__device__ int   g_bsum[NBMAX];
__device__ float g_sum[F];
__device__ float g_sumsq[F];
__device__ float g_scale[F];
__device__ float g_shift[F];
__device__ int   g_is64;

// ---------------- helpers ----------------
__device__ __forceinline__ uint32_t smem_u32(const void* p) {
    uint32_t a;
    asm("{ .reg .u64 t; cvta.to.shared.u64 t, %1; cvt.u32.u64 %0, t; }"
        : "=r"(a) : "l"(p));
    return a;
}
__device__ __forceinline__ void split_bf16(float v, __nv_bfloat16& h, __nv_bfloat16& l) {
    h = __float2bfloat16(v);
    l = __float2bfloat16(v - __bfloat162float(h));
}
__device__ __forceinline__ uint32_t pack_bf162(__nv_bfloat16 a, __nv_bfloat16 b) {
    __nv_bfloat162 p = __halves2bfloat162(a, b);
    return *reinterpret_cast<uint32_t*>(&p);
}

#define LDMX4(r0, r1, r2, r3, addr) \
    asm volatile("ldmatrix.sync.aligned.m8n8.x4.shared.b16 {%0,%1,%2,%3}, [%4];" \
        : "=r"(r0), "=r"(r1), "=r"(r2), "=r"(r3) : "r"(addr))
#define LDMX4T(r0, r1, r2, r3, addr) \
    asm volatile("ldmatrix.sync.aligned.m8n8.x4.trans.shared.b16 {%0,%1,%2,%3}, [%4];" \
        : "=r"(r0), "=r"(r1), "=r"(r2), "=r"(r3) : "r"(addr))
#define MMA16816(c, a, b0, b1) \
    asm volatile("mma.sync.aligned.m16n8k16.row.col.f32.bf16.bf16.f32 " \
        "{%0,%1,%2,%3}, {%4,%5,%6,%7}, {%8,%9}, {%0,%1,%2,%3};" \
        : "+f"((c)[0]), "+f"((c)[1]), "+f"((c)[2]), "+f"((c)[3]) \
        : "r"((a)[0]), "r"((a)[1]), "r"((a)[2]), "r"((a)[3]), "r"(b0), "r"(b1))

// ---------------- detect edge_index dtype (int64 vs silently-int32) -------
__global__ void detect_kernel(const void* ei, int n) {
    if (threadIdx.x == 0 && blockIdx.x == 0) {
        const long long* p = (const long long*)ei;
        int ok = 1;
#pragma unroll
        for (int i = 0; i < 16; i++) {
            long long v = p[i];
            if (v < 0 || v >= n) { ok = 0; break; }
        }
        g_is64 = ok;
    }
}

// ---------------- init ----------------
__global__ void init_kernel(int n) {
    int i = blockIdx.x * blockDim.x + threadIdx.x;
    if (i < n) g_deg[i] = 0;
    if (i < F) { g_sum[i] = 0.f; g_sumsq[i] = 0.f; }
}

// ---------------- degree histogram over destination (col) ----------------
__global__ void deg_kernel(const void* __restrict__ ei, int E) {
    int e = blockIdx.x * blockDim.x + threadIdx.x;
    if (e < E) {
        int c;
        if (g_is64) c = (int)((const long long*)ei)[E + e];
        else        c = ((const int*)ei)[E + e];
        atomicAdd(&g_deg[c], 1);
    }
}

// ---------------- 3-phase scan ----------------
__global__ void scan1_kernel(int n) {
    __shared__ int wsum[32];
    const int t = threadIdx.x;
    const int lane = t & 31;
    const int w = t >> 5;
    const int idx = blockIdx.x * SCAN_BLK + t * 4;

    int d0 = 0, d1 = 0, d2 = 0, d3 = 0;
    if (idx + 3 < n) {
        int4 dd = *(const int4*)&g_deg[idx];
        d0 = dd.x; d1 = dd.y; d2 = dd.z; d3 = dd.w;
    } else {
        if (idx + 0 < n) d0 = g_deg[idx + 0];
        if (idx + 1 < n) d1 = g_deg[idx + 1];
        if (idx + 2 < n) d2 = g_deg[idx + 2];
        if (idx + 3 < n) d3 = g_deg[idx + 3];
    }
    int s = d0 + d1 + d2 + d3;
    int v = s;
#pragma unroll
    for (int o = 1; o < 32; o <<= 1) {
        int a = __shfl_up_sync(0xffffffffu, v, o);
        if (lane >= o) v += a;
    }
    if (lane == 31) wsum[w] = v;
    __syncthreads();
    if (w == 0) {
        int sv = wsum[lane];
#pragma unroll
        for (int o = 1; o < 32; o <<= 1) {
            int a = __shfl_up_sync(0xffffffffu, sv, o);
            if (lane >= o) sv += a;
        }
        wsum[lane] = sv;
    }
    __syncthreads();
    int excl = (w ? wsum[w - 1] : 0) + v - s;

    if (idx + 3 < n) {
        int4 oo = make_int4(excl, excl + d0, excl + d0 + d1, excl + d0 + d1 + d2);
        *(int4*)&g_off[idx] = oo;
        g_dinv[idx + 0] = rsqrtf((float)(d0 + 1));
        g_dinv[idx + 1] = rsqrtf((float)(d1 + 1));
        g_dinv[idx + 2] = rsqrtf((float)(d2 + 1));
        g_dinv[idx + 3] = rsqrtf((float)(d3 + 1));
    } else {
        int e = excl;
        if (idx + 0 < n) { g_off[idx + 0] = e; g_dinv[idx + 0] = rsqrtf((float)(d0 + 1)); e += d0; }
        if (idx + 1 < n) { g_off[idx + 1] = e; g_dinv[idx + 1] = rsqrtf((float)(d1 + 1)); e += d1; }
        if (idx + 2 < n) { g_off[idx + 2] = e; g_dinv[idx + 2] = rsqrtf((float)(d2 + 1)); e += d2; }
        if (idx + 3 < n) { g_off[idx + 3] = e; g_dinv[idx + 3] = rsqrtf((float)(d3 + 1)); }
    }
    if (t == 0) g_bsum[blockIdx.x] = wsum[31];
}

__global__ void scan2_kernel(int nb) {
    int lane = threadIdx.x;
    int v = (lane < nb) ? g_bsum[lane] : 0;
    int orig = v;
#pragma unroll
    for (int o = 1; o < 32; o <<= 1) {
        int a = __shfl_up_sync(0xffffffffu, v, o);
        if (lane >= o) v += a;
    }
    if (lane < nb) g_bsum[lane] = v - orig;
}

__global__ void scan3_kernel(int n) {
    int i = blockIdx.x * blockDim.x + threadIdx.x;
    if (i < n) {
        int o = g_off[i] + g_bsum[i >> 12];
        g_off[i] = o;
        g_cur[i] = o;
    }
}

// ---------------- CSR fill ----------------
__global__ void fill_kernel(const void* __restrict__ ei, int E) {
    int e = blockIdx.x * blockDim.x + threadIdx.x;
    if (e < E) {
        int r, c;
        if (g_is64) {
            r = (int)((const long long*)ei)[e];
            c = (int)((const long long*)ei)[E + e];
        } else {
            r = ((const int*)ei)[e];
            c = ((const int*)ei)[E + e];
        }
        int p = atomicAdd(&g_cur[c], 1);
        g_src[p] = r;
    }
}

// ---------------- mma.sync bf16 dual GEMM ---------------------------------
// Block: 256 threads (8 warps, 2x4), tile 64 rows x 256 cols (W | W_res).
// K chunked by 16. hi/lo bf16 split: ah*bh + ah*bl + al*bh (rel err ~1e-5).
// Warp tile 32x64: A frags 2 (m16k16), B frags 8 (k16n8), acc 16 x m16n8.
#define GM 64
#define GKC 16
#define LDAB 48          // A smem row stride in bf16 (96 B)
#define LDBB 272         // B smem row stride in bf16 (544 B)

__global__ void __launch_bounds__(256)
gemm_mma_kernel(const float* __restrict__ X,
                const float* __restrict__ Wm,
                const float* __restrict__ Wres,
                const float* __restrict__ b_res,
                float* __restrict__ out, int n) {
    __shared__ __align__(16) __nv_bfloat16 sAh[GM * LDAB];    // 6 KB
    __shared__ __align__(16) __nv_bfloat16 sAl[GM * LDAB];    // 6 KB
    __shared__ __align__(16) __nv_bfloat16 sBh[GKC * LDBB];   // 8.5 KB
    __shared__ __align__(16) __nv_bfloat16 sBl[GKC * LDBB];   // 8.5 KB

    const int tid = threadIdx.x;
    const int lane = tid & 31;
    const int wid = tid >> 5;
    const int warpM = wid >> 2;          // 0..1
    const int warpN = wid & 3;           // 0..3
    const int block_row = blockIdx.x * GM;

    char* sAh_b = (char*)sAh;
    char* sAl_b = (char*)sAl;
    char* sBh_b = (char*)sBh;
    char* sBl_b = (char*)sBl;
    const uint32_t uAh = smem_u32(sAh);
    const uint32_t uAl = smem_u32(sAl);
    const uint32_t uBh = smem_u32(sBh);
    const uint32_t uBl = smem_u32(sBl);

    float acc[2][8][4];
#pragma unroll
    for (int i = 0; i < 2; i++)
#pragma unroll
        for (int j = 0; j < 8; j++)
#pragma unroll
            for (int q = 0; q < 4; q++) acc[i][j][q] = 0.f;

    // precomputed ldmatrix addresses
    uint32_t a_addr[2];
#pragma unroll
    for (int mf = 0; mf < 2; mf++) {
        int row = warpM * 32 + mf * 16 + (lane & 15);
        a_addr[mf] = row * (LDAB * 2) + (lane >> 4) * 16;
    }
    uint32_t b_addr[4];
#pragma unroll
    for (int nf2 = 0; nf2 < 4; nf2++) {
        int k = lane & 15;
        int col = warpN * 64 + nf2 * 16 + (lane >> 4) * 8;
        b_addr[nf2] = k * (LDBB * 2) + col * 2;
    }

    for (int kc = 0; kc < F; kc += GKC) {
        __syncthreads();
        // ---- A chunk: 64 rows x 16 k ----
        {
            int row = tid >> 2;
            int kq = tid & 3;
            int gr = block_row + row;
            float4 v = make_float4(0.f, 0.f, 0.f, 0.f);
            if (gr < n) v = *(const float4*)&X[(size_t)gr * F + kc + kq * 4];
            __nv_bfloat16 h0, l0, h1, l1, h2, l2, h3, l3;
            split_bf16(v.x, h0, l0); split_bf16(v.y, h1, l1);
            split_bf16(v.z, h2, l2); split_bf16(v.w, h3, l3);
            int off = row * (LDAB * 2) + kq * 8;
            *(uint32_t*)(sAh_b + off)     = pack_bf162(h0, h1);
            *(uint32_t*)(sAh_b + off + 4) = pack_bf162(h2, h3);
            *(uint32_t*)(sAl_b + off)     = pack_bf162(l0, l1);
            *(uint32_t*)(sAl_b + off + 4) = pack_bf162(l2, l3);
        }
        // ---- B chunk: 16 k x 256 cols (W | W_res) ----
#pragma unroll
        for (int j = 0; j < 4; j++) {
            int idx = j * 256 + tid;         // 0..1023
            int k = idx >> 6;                // 0..15
            int nn = (idx & 63) * 4;         // 0..252
            const float* src = (nn < 128)
                ? &Wm[(size_t)(kc + k) * F + nn]
                : &Wres[(size_t)(kc + k) * F + nn - 128];
            float4 v = *(const float4*)src;
            __nv_bfloat16 h0, l0, h1, l1, h2, l2, h3, l3;
            split_bf16(v.x, h0, l0); split_bf16(v.y, h1, l1);
            split_bf16(v.z, h2, l2); split_bf16(v.w, h3, l3);
            int off = k * (LDBB * 2) + nn * 2;
            *(uint32_t*)(sBh_b + off)     = pack_bf162(h0, h1);
            *(uint32_t*)(sBh_b + off + 4) = pack_bf162(h2, h3);
            *(uint32_t*)(sBl_b + off)     = pack_bf162(l0, l1);
            *(uint32_t*)(sBl_b + off + 4) = pack_bf162(l2, l3);
        }
        __syncthreads();

        // ---- fragments + mma ----
        uint32_t ah[2][4], al[2][4];
#pragma unroll
        for (int mf = 0; mf < 2; mf++) {
            LDMX4(ah[mf][0], ah[mf][1], ah[mf][2], ah[mf][3], uAh + a_addr[mf]);
            LDMX4(al[mf][0], al[mf][1], al[mf][2], al[mf][3], uAl + a_addr[mf]);
        }
#pragma unroll
        for (int nf2 = 0; nf2 < 4; nf2++) {
            uint32_t bh[4], bl[4];
            LDMX4T(bh[0], bh[1], bh[2], bh[3], uBh + b_addr[nf2]);
            LDMX4T(bl[0], bl[1], bl[2], bl[3], uBl + b_addr[nf2]);
#pragma unroll
            for (int half = 0; half < 2; half++) {
                int nf = nf2 * 2 + half;
#pragma unroll
                for (int mf = 0; mf < 2; mf++) {
                    MMA16816(acc[mf][nf], ah[mf], bh[half * 2], bh[half * 2 + 1]);
                    MMA16816(acc[mf][nf], ah[mf], bl[half * 2], bl[half * 2 + 1]);
                    MMA16816(acc[mf][nf], al[mf], bh[half * 2], bh[half * 2 + 1]);
                }
            }
        }
    }

    // ---- epilogue: direct register stores ----
#pragma unroll
    for (int mf = 0; mf < 2; mf++) {
        int gr0 = block_row + warpM * 32 + mf * 16 + (lane >> 2);
#pragma unroll
        for (int nf = 0; nf < 8; nf++) {
            int cg = warpN * 64 + nf * 8 + (lane & 3) * 2;
            float bias0 = 0.f, bias1 = 0.f;
            float* dst;
            int col;
            if (cg < 128) {
                dst = g_h; col = cg;
            } else {
                dst = out; col = cg - 128;
                bias0 = b_res[col];
                bias1 = b_res[col + 1];
            }
            if (gr0 < n) {
                float2 o = make_float2(acc[mf][nf][0] + bias0,
                                       acc[mf][nf][1] + bias1);
                *(float2*)&dst[(size_t)gr0 * F + col] = o;
            }
            if (gr0 + 8 < n) {
                float2 o = make_float2(acc[mf][nf][2] + bias0,
                                       acc[mf][nf][3] + bias1);
                *(float2*)&dst[(size_t)(gr0 + 8) * F + col] = o;
            }
        }
    }
}

// ---------------- aggregate (gather) + self-loop + bias + ReLU + BN stats --
__global__ void aggregate_kernel(const float* __restrict__ b, int n) {
    __shared__ float bsum[F];
    __shared__ float bsq[F];
    const int t = threadIdx.x;
    if (t < F) { bsum[t] = 0.f; bsq[t] = 0.f; }
    __syncthreads();

    const int node = (blockIdx.x * blockDim.x + t) >> 5;
    const int lane = t & 31;

    if (node < n) {
        const float4* h4 = (const float4*)g_h;
        float dc = g_dinv[node];
        float dc2 = dc * dc;
        int j = g_off[node];
        int end = j + g_deg[node];

        float4 acc = h4[(size_t)node * 32 + lane];
        float4 bv = ((const float4*)b)[lane];
        acc.x = fmaf(acc.x, dc2, bv.x);
        acc.y = fmaf(acc.y, dc2, bv.y);
        acc.z = fmaf(acc.z, dc2, bv.z);
        acc.w = fmaf(acc.w, dc2, bv.w);

        for (; j < end; j++) {
            int r = g_src[j];
            float nrm = dc * g_dinv[r];
            float4 v = h4[(size_t)r * 32 + lane];
            acc.x = fmaf(v.x, nrm, acc.x);
            acc.y = fmaf(v.y, nrm, acc.y);
            acc.z = fmaf(v.z, nrm, acc.z);
            acc.w = fmaf(v.w, nrm, acc.w);
        }
        acc.x = fmaxf(acc.x, 0.f);
        acc.y = fmaxf(acc.y, 0.f);
        acc.z = fmaxf(acc.z, 0.f);
        acc.w = fmaxf(acc.w, 0.f);
        ((float4*)g_agg)[(size_t)node * 32 + lane] = acc;

        int f0 = lane * 4;
        atomicAdd(&bsum[f0 + 0], acc.x);
        atomicAdd(&bsum[f0 + 1], acc.y);
        atomicAdd(&bsum[f0 + 2], acc.z);
        atomicAdd(&bsum[f0 + 3], acc.w);
        atomicAdd(&bsq[f0 + 0], acc.x * acc.x);
        atomicAdd(&bsq[f0 + 1], acc.y * acc.y);
        atomicAdd(&bsq[f0 + 2], acc.z * acc.z);
        atomicAdd(&bsq[f0 + 3], acc.w * acc.w);
    }
    __syncthreads();
    if (t < F) {
        atomicAdd(&g_sum[t], bsum[t]);
        atomicAdd(&g_sumsq[t], bsq[t]);
    }
}

// ---------------- fold mean/var/gamma/beta into scale/shift ----------------
__global__ void finalize_stats_kernel(const float* __restrict__ gamma,
                                      const float* __restrict__ beta, int n) {
    int f = threadIdx.x;
    if (f < F) {
        float inv_n = 1.f / (float)n;
        float mean = g_sum[f] * inv_n;
        float var = g_sumsq[f] * inv_n - mean * mean;
        float istd = rsqrtf(var + BN_EPS);
        float sc = gamma[f] * istd;
        g_scale[f] = sc;
        g_shift[f] = beta[f] - mean * sc;
    }
}

// ---------------- final: out += r*scale + shift (out holds res+b_res) -----
__global__ void final_kernel(float* __restrict__ out, int n) {
    int tid = blockIdx.x * blockDim.x + threadIdx.x;
    if (tid >= n * (F / 4)) return;
    int s = tid & 31;
    float4 a = ((const float4*)g_agg)[tid];
    float4 sc = ((const float4*)g_scale)[s];
    float4 sh = ((const float4*)g_shift)[s];
    float4 o = ((float4*)out)[tid];
    o.x += a.x * sc.x + sh.x;
    o.y += a.y * sc.y + sh.y;
    o.z += a.z * sc.z + sh.z;
    o.w += a.w * sc.w + sh.w;
    ((float4*)out)[tid] = o;
}

// ---------------- launch (kernel launches ONLY) ----------------------------
extern "C" void kernel_launch(void* const* d_in, const int* in_sizes, int n_in,
                              void* d_out, int out_size) {
    const float* x        = (const float*)d_in[0];
    const void*  ei       = d_in[1];
    const float* W        = (const float*)d_in[2];
    const float* b        = (const float*)d_in[3];
    const float* gamma    = (const float*)d_in[4];
    const float* beta     = (const float*)d_in[5];
    const float* W_res    = (const float*)d_in[6];
    const float* b_res    = (const float*)d_in[7];
    float* out            = (float*)d_out;

    const int n = in_sizes[0] / F;
    const int E = in_sizes[1] / 2;
    const int nb = (n + SCAN_BLK - 1) / SCAN_BLK;

    const int T = 256;
    detect_kernel<<<1, 32>>>(ei, n);                       // 1
    init_kernel<<<(n + T - 1) / T, T>>>(n);                // 2
    deg_kernel<<<(E + T - 1) / T, T>>>(ei, E);             // 3
    gemm_mma_kernel<<<(n + GM - 1) / GM, 256>>>(x, W, W_res, b_res, out, n); // 4
    scan1_kernel<<<nb, 1024>>>(n);                         // 5
    scan2_kernel<<<1, 32>>>(nb);                           // 6
    scan3_kernel<<<(n + T - 1) / T, T>>>(n);               // 7
    fill_kernel<<<(E + T - 1) / T, T>>>(ei, E);            // 8
    {
        long long work = (long long)n * 32;
        aggregate_kernel<<<(int)((work + T - 1) / T), T>>>(b, n);   // 9
    }
    finalize_stats_kernel<<<1, F>>>(gamma, beta, n);       // 10
    {
        int work = n * (F / 4);
        final_kernel<<<(work + T - 1) / T, T>>>(out, n);   // 11
    }
}